// round 6
// baseline (speedup 1.0000x reference)
#include <cuda_runtime.h>
#include <cstdint>

// Problem shape (fixed by the reference):
//   graph_lstm_output: [B=4, S=256, C=128] f32   (d_in[0])
//   slic_output:       [B=4, H=512, W=512] i32   (d_in[1])
//   out:               [B, H, W, C] f32
//
// out[b,h,w,:] = graph_lstm_output[b, slic[b,h,w]-1, :]
//
// R5: unroll-based MLP capped by register allocation (regs=32 => ~4 chains).
// New plan: per-batch table (128 KB) staged in SMEM; gather served by LDS
// (29 cyc) instead of L2 (~250 cyc). 148 CTAs (1/SM), 37 per batch, 1024 thr.

static constexpr int S = 256;
static constexpr int C = 128;                    // 32 float4 per segment row
static constexpr int PIX_PER_BATCH = 512 * 512;  // 2^18
static constexpr int NCTA = 148;                 // 1 CTA per SM
static constexpr int CTAS_PER_BATCH = 37;        // 148 / 4
static constexpr int TPB = 1024;                 // 32 warps
static constexpr int PIX_PER_CTA = 7088;         // ceil(2^18/37) rounded to 16
static constexpr int TABLE_F4 = S * (C / 4);     // 8192 float4 = 128 KB
static constexpr int SMEM_BYTES = TABLE_F4 * 16; // 131072

__global__ __launch_bounds__(TPB, 1)
void convert2image_smem(const float4* __restrict__ src,   // [4*S, 32] float4
                        const int*    __restrict__ slic,  // [4, 2^18]
                        float4*       __restrict__ out)   // [4, 2^18, 32]
{
    extern __shared__ float4 s_table[];   // [S, 32] = 128 KB

    const unsigned b   = blockIdx.x & 3;          // batch
    const unsigned sub = blockIdx.x >> 2;         // 0..36 within batch
    const unsigned tid  = threadIdx.x;
    const unsigned lane = tid & 31;
    const unsigned wid  = tid >> 5;

    // Stage this batch's table slice into SMEM (coalesced, 8 f4 per thread).
    {
        const float4* tb = src + (b << 13);       // b * 8192 float4
        #pragma unroll
        for (int i = 0; i < TABLE_F4 / TPB; i++)
            s_table[tid + i * TPB] = tb[tid + i * TPB];
    }
    __syncthreads();

    const unsigned pstart = sub * PIX_PER_CTA;
    const unsigned pend   = min(pstart + (unsigned)PIX_PER_CTA,
                                (unsigned)PIX_PER_BATCH);

    const int*    sl = slic + (b << 18);
    float4*       ob = out  + (b << 23);          // b * 2^18 * 32 float4

    // Each warp takes 4 consecutive pixels per iteration (one uniform int4
    // slic load = 1 sector per 2 KB of output), 32 warps stride the range.
    for (unsigned p0 = pstart + (wid << 2); p0 < pend; p0 += TPB / 32 * 4) {
        // pstart and pend are 16-aligned, so p0 < pend implies p0+3 < pend.
        int4 s4 = __ldcs(reinterpret_cast<const int4*>(sl + p0));

        // Conflict-free LDS.128 (each phase reads 128 consecutive bytes),
        // then coalesced streaming STG.128 (write-once, evict-first).
        float4 v0 = s_table[(((unsigned)(s4.x - 1)) << 5) + lane];
        float4 v1 = s_table[(((unsigned)(s4.y - 1)) << 5) + lane];
        float4 v2 = s_table[(((unsigned)(s4.z - 1)) << 5) + lane];
        float4 v3 = s_table[(((unsigned)(s4.w - 1)) << 5) + lane];

        unsigned o = (p0 << 5) + lane;
        __stcs(&ob[o],       v0);
        __stcs(&ob[o + 32],  v1);
        __stcs(&ob[o + 64],  v2);
        __stcs(&ob[o + 96],  v3);
    }
}

extern "C" void kernel_launch(void* const* d_in, const int* in_sizes, int n_in,
                              void* d_out, int out_size)
{
    const float4* src  = (const float4*)d_in[0];
    const int*    slic = (const int*)d_in[1];
    float4*       out  = (float4*)d_out;

    // 128 KB dynamic smem needs the opt-in (idempotent; not a stream op).
    static bool attr_set = false;
    if (!attr_set) {
        cudaFuncSetAttribute(convert2image_smem,
                             cudaFuncAttributeMaxDynamicSharedMemorySize,
                             SMEM_BYTES);
        attr_set = true;
    }

    convert2image_smem<<<NCTA, TPB, SMEM_BYTES>>>(src, slic, out);
}

// round 7
// speedup vs baseline: 1.2376x; 1.2376x over previous
#include <cuda_runtime.h>
#include <cstdint>

// out[b,h,w,:] = graph_lstm_output[b, slic[b,h,w]-1, :]
//   graph_lstm_output: [B=4, S=256, C=128] f32   (d_in[0])
//   slic_output:       [B=4, 512, 512] i32       (d_in[1])
//
// R6 failed (117us): smem table was right, but slic load was loop-carried
// (MLP=1/warp -> issue 6%). R7: one coalesced LDG.32 covers 32 pixels/warp,
// prefetched one iteration ahead; segments broadcast via shfl; gather served
// by conflict-free LDS (kills the 512 MB L2 gather-read stream entirely).

static constexpr int S = 256;
static constexpr int C = 128;                    // 32 float4 per segment row
static constexpr int PIX_PER_BATCH = 512 * 512;  // 2^18
static constexpr int NCTA = 148;                 // 1 CTA per SM (128 KB smem)
static constexpr int CTAS_PER_BATCH = 37;
static constexpr int TPB = 1024;                 // 32 warps
static constexpr int PIX_PER_CTA = 7104;         // 222*32; 37*7104 >= 2^18
static constexpr int TABLE_F4 = S * (C / 4);     // 8192 float4 = 128 KB
static constexpr int SMEM_BYTES = TABLE_F4 * 16; // 131072
static constexpr int WPIX = 32;                  // pixels per warp-iteration
static constexpr unsigned STRIDE = (TPB / 32) * WPIX;  // 1024 pixels / CTA-iter

__global__ __launch_bounds__(TPB, 1)
void convert2image_smem_pipe(const float4* __restrict__ src,   // [4*S, 32] f4
                             const int*    __restrict__ slic,  // [4, 2^18]
                             float4*       __restrict__ out)   // [4,2^18,32]
{
    extern __shared__ float4 s_table[];   // [S, 32] = 128 KB

    const unsigned b    = blockIdx.x & 3;     // batch
    const unsigned sub  = blockIdx.x >> 2;    // 0..36 within batch
    const unsigned tid  = threadIdx.x;
    const unsigned lane = tid & 31;
    const unsigned wid  = tid >> 5;

    // Stage this batch's 128 KB table slice (coalesced, 8 f4 per thread).
    {
        const float4* tb = src + (b << 13);   // b * 8192 float4
        #pragma unroll
        for (int i = 0; i < TABLE_F4 / TPB; i++)
            s_table[tid + i * TPB] = tb[tid + i * TPB];
    }
    __syncthreads();

    const unsigned pstart = sub * PIX_PER_CTA;
    const unsigned pend   = min(pstart + (unsigned)PIX_PER_CTA,
                                (unsigned)PIX_PER_BATCH);
    // pend - pstart is a multiple of 32; every in-range p0 has 32 full pixels.

    const int*  sl = slic + (b << 18);
    float4*     ob = out  + (b << 23);        // b * 2^18 * 32 float4

    unsigned p0 = pstart + wid * WPIX;
    if (p0 >= pend) return;

    // Prime the pipeline: lane i holds segment id of pixel p0+i.
    int s = __ldcs(sl + p0 + lane);

    for (; p0 < pend; ) {
        int s_cur = s;
        unsigned pn = p0 + STRIDE;
        // Prefetch next iteration's 32 segment ids (latency hidden behind
        // the 16 KB of LDS+STG work below).
        if (pn < pend) s = __ldcs(sl + pn + lane);

        unsigned obase = (p0 << 5) + lane;
        #pragma unroll
        for (int i = 0; i < WPIX; i++) {
            int seg = __shfl_sync(0xffffffffu, s_cur, i) - 1;
            // Conflict-free LDS.128: 32 lanes read 512 consecutive bytes.
            float4 v = s_table[(((unsigned)seg) << 5) + lane];
            // Coalesced streaming store (write-once, evict-first).
            __stcs(&ob[obase + ((unsigned)i << 5)], v);
        }
        p0 = pn;
    }
}

extern "C" void kernel_launch(void* const* d_in, const int* in_sizes, int n_in,
                              void* d_out, int out_size)
{
    const float4* src  = (const float4*)d_in[0];
    const int*    slic = (const int*)d_in[1];
    float4*       out  = (float4*)d_out;

    static bool attr_set = false;
    if (!attr_set) {
        cudaFuncSetAttribute(convert2image_smem_pipe,
                             cudaFuncAttributeMaxDynamicSharedMemorySize,
                             SMEM_BYTES);
        attr_set = true;
    }

    convert2image_smem_pipe<<<NCTA, TPB, SMEM_BYTES>>>(src, slic, out);
}

// round 8
// speedup vs baseline: 1.4607x; 1.1803x over previous
#include <cuda_runtime.h>
#include <cstdint>

// out[b,h,w,:] = graph_lstm_output[b, slic[b,h,w]-1, :]
//   graph_lstm_output: [B=4, S=256, C=128] f32   (d_in[0])
//   slic_output:       [B=4, 512, 512] i32       (d_in[1])
//
// R3 (80.4us) was LTS-capped: gather reads (512 MB, L2 hits) + writes
// (512 MB) + DRAM fill = ~12.8 TB/s combined L2 traffic ~= the ~11 TB/s
// measured LTS cap. R3's chunk stride also made each thread touch all 4
// batches' tables (512 KB > L1). R8: restride chunks WITHIN one batch so
// each SM's working set is one 128 KB table -> L1-resident gathers, and the
// 512 MB read stream leaves L2 entirely, freeing the fabric for writes.

static constexpr int B = 4;
static constexpr int S = 256;
static constexpr int C = 128;                    // 32 float4 per segment row
static constexpr unsigned F4_PER_BATCH = 1u << 23;   // 2^18 pix * 32 f4
static constexpr int UNROLL = 4;
static constexpr unsigned CHUNK = F4_PER_BATCH / UNROLL;  // 2^21 f4
static constexpr unsigned THREADS_TOTAL = 1u << 23;       // 2^25 f4 / 4

__global__ __launch_bounds__(256)
void convert2image_l1(const float4* __restrict__ src,   // [B*S, 32] float4
                      const int*    __restrict__ slic,  // [B, 2^18]
                      float4*       __restrict__ out)   // [B, 2^18, 32]
{
    const unsigned t = blockIdx.x * blockDim.x + threadIdx.x;  // [0, 2^23)

    const unsigned b   = t >> 21;              // batch: 2^21 threads per batch
    const unsigned loc = t & (CHUNK - 1u);     // local f4 base within batch
    const unsigned lane = loc & 31;            // CHUNK is 32-aligned

    const int*    sl = slic + (b << 18);
    const float4* tb = src  + (b << 13);       // this batch's table (128 KB)
    float4*       ob = out  + (b << 23);

    // Phase 1: 4 independent slic loads within this batch (pixel stride 2^16).
    // __ldcs keeps the streamed index data out of L1 (reserved for the table).
    const float4* rowp[UNROLL];
    #pragma unroll
    for (int i = 0; i < UNROLL; i++) {
        unsigned pix = (loc + (unsigned)i * CHUNK) >> 5;
        int seg = __ldcs(&sl[pix]) - 1;        // 0-based segment
        rowp[i] = tb + (((unsigned)seg) << 5); // seg * 32 float4
    }

    // Phase 2: 4 independent gathers — same 128 KB table for all 4, shared by
    // every CTA on this SM -> L1-resident after warmup (~39 cyc, no L2 trip).
    float4 v[UNROLL];
    #pragma unroll
    for (int i = 0; i < UNROLL; i++)
        v[i] = __ldg(&rowp[i][lane]);

    // Phase 3: 4 coalesced streaming stores (write-once, evict-first).
    #pragma unroll
    for (int i = 0; i < UNROLL; i++)
        __stcs(&ob[loc + (unsigned)i * CHUNK], v[i]);
}

extern "C" void kernel_launch(void* const* d_in, const int* in_sizes, int n_in,
                              void* d_out, int out_size)
{
    const float4* src  = (const float4*)d_in[0];
    const int*    slic = (const int*)d_in[1];
    float4*       out  = (float4*)d_out;

    const int threads = 256;
    const int blocks  = THREADS_TOTAL / threads;  // 32768; 8192 contiguous
                                                  // blocks per batch
    convert2image_l1<<<blocks, threads>>>(src, slic, out);
}